// round 3
// baseline (speedup 1.0000x reference)
#include <cuda_runtime.h>
#include <cstdint>

#define NN 50000
#define NE 1200000
#define INC 128
#define HC 64
#define OC 64

typedef unsigned long long ull;

// ---------------- scratch (static device globals; 16B-aligned for vector LDG/STG) ----------------
__device__ __align__(16) float g_xl[(size_t)NN * HC];       // x @ W_l^T
__device__ __align__(16) float g_xr[(size_t)NN * HC];       // x @ W_r^T
__device__ __align__(16) float g_hid[(size_t)NN * HC];      // post-aggregation hidden (after bias+ELU)
__device__ __align__(16) float g_Wt[INC * 128];             // transposed weights [k][ch], ch<64 = W_l, else W_r
__device__ __align__(16) float g_Wlt[HC * OC];              // transposed W_lin [k][o]
__device__ int   g_cnt[NN];
__device__ int   g_off[NN + 1];
__device__ int   g_cur[NN];
__device__ int   g_srcs[NE];
__device__ int   g_probe;   // OR of odd 32-bit words of edge_index; 0 => data is int64

// ---------------- packed f32x2 helpers ----------------
__device__ __forceinline__ ull pack2(float lo, float hi) {
    ull r;
    asm("mov.b64 %0, {%1, %2};" : "=l"(r) : "f"(lo), "f"(hi));
    return r;
}
__device__ __forceinline__ void unpack2(ull v, float& lo, float& hi) {
    asm("mov.b64 {%0, %1}, %2;" : "=f"(lo), "=f"(hi) : "l"(v));
}
__device__ __forceinline__ void ffma2(ull& d, ull a, ull b) {
    asm("fma.rn.f32x2 %0, %1, %2, %0;" : "+l"(d) : "l"(a), "l"(b));
}

// edge-index load that works for both int32 and int64 storage
__device__ __forceinline__ int load_idx(const void* ei, int pos, int is64) {
    int v = is64 ? (int)((const long long*)ei)[pos] : ((const int*)ei)[pos];
    // clamp: a wrong dtype guess must yield a wrong answer, not a crash
    return (v < 0) ? 0 : (v >= NN ? NN - 1 : v);
}

// ---------------- K0: weight transpose + count zero + probe reset ----------------
__global__ void k_pre(const float* __restrict__ Wl, const float* __restrict__ Wr,
                      const float* __restrict__ Wlin) {
    int stride = gridDim.x * blockDim.x;
    int t0 = blockIdx.x * blockDim.x + threadIdx.x;
    if (t0 == 0) g_probe = 0;
    for (int t = t0; t < NN; t += stride) {
        g_cnt[t] = 0;
        if (t < INC * 128) {
            int k = t >> 7, ch = t & 127;
            g_Wt[t] = (ch < HC) ? Wl[ch * INC + k] : Wr[(ch - HC) * INC + k];
        }
        if (t < HC * OC) {
            int k = t >> 6, o = t & 63;
            g_Wlt[t] = Wlin[o * HC + k];
        }
    }
}

// ---------------- K0b: dtype probe over first 2*NE 32-bit words ----------------
// If edge_index is int64 (values < 2^31, non-negative), every odd word is 0.
__global__ void k_detect(const int* __restrict__ w) {
    int stride = gridDim.x * blockDim.x;
    int v = 0;
    for (int i = blockIdx.x * blockDim.x + threadIdx.x; i < NE; i += stride)
        v |= w[2 * i + 1];
#pragma unroll
    for (int o = 16; o; o >>= 1) v |= __shfl_xor_sync(0xffffffffu, v, o);
    if ((threadIdx.x & 31) == 0 && v) atomicOr(&g_probe, 1);
}

// ---------------- K1: fused xl/xr projection GEMM ----------------
// block = 128 threads (4 warps). Each warp: 8 rows (4 row-pairs) x all 128 output
// channels (64 xl + 64 xr). Row-pairs packed in f32x2 accumulators.
__global__ void k_gemm1(const float* __restrict__ x) {
    __shared__ __align__(16) float xs2[32 * INC];  // pair-interleaved: [rp][k][rb]
    int tid = threadIdx.x;
    int row0 = blockIdx.x * 32;
    int nrows = NN - row0; if (nrows > 32) nrows = 32;

    for (int i = tid; i < 32 * (INC / 4); i += 128) {
        int r = i >> 5;               // 32 float4 per row
        int k4 = (i & 31) << 2;
        if (r < nrows) {
            float4 v = *(const float4*)(x + (size_t)(row0 + r) * INC + k4);
            float* b = xs2 + (r >> 1) * (2 * INC) + (r & 1);
            b[2 * k4 + 0] = v.x; b[2 * k4 + 2] = v.y;
            b[2 * k4 + 4] = v.z; b[2 * k4 + 6] = v.w;
        }
    }
    __syncthreads();

    int warp = tid >> 5, lane = tid & 31;
    int c = lane << 2;                 // channels c..c+3 (c<64 -> xl, else xr)
    ull acc[4][4];
#pragma unroll
    for (int q = 0; q < 4; q++)
#pragma unroll
        for (int j = 0; j < 4; j++) acc[q][j] = 0ull;

    const float* xb = xs2 + (warp * 4) * (2 * INC);
#pragma unroll 8
    for (int k = 0; k < INC; k++) {
        float4 w = *(const float4*)(g_Wt + (k << 7) + c);
        ull w0 = pack2(w.x, w.x), w1 = pack2(w.y, w.y);
        ull w2 = pack2(w.z, w.z), w3 = pack2(w.w, w.w);
#pragma unroll
        for (int q = 0; q < 4; q++) {
            ull xp = *(const ull*)(xb + q * (2 * INC) + 2 * k);
            ffma2(acc[q][0], xp, w0);
            ffma2(acc[q][1], xp, w1);
            ffma2(acc[q][2], xp, w2);
            ffma2(acc[q][3], xp, w3);
        }
    }

    float* base = (c < HC) ? (g_xl + c) : (g_xr + (c - HC));
#pragma unroll
    for (int q = 0; q < 4; q++) {
        int re = row0 + warp * 8 + q * 2;
        if (re >= NN) break;
        float lo0, hi0, lo1, hi1, lo2, hi2, lo3, hi3;
        unpack2(acc[q][0], lo0, hi0); unpack2(acc[q][1], lo1, hi1);
        unpack2(acc[q][2], lo2, hi2); unpack2(acc[q][3], lo3, hi3);
        *(float4*)(base + (size_t)re * HC) = make_float4(lo0, lo1, lo2, lo3);
        if (re + 1 < NN)
            *(float4*)(base + (size_t)(re + 1) * HC) = make_float4(hi0, hi1, hi2, hi3);
    }
}

// ---------------- K2: degree histogram ----------------
__global__ void k_hist(const void* __restrict__ ei) {
    int is64 = (g_probe == 0);
    int e = blockIdx.x * blockDim.x + threadIdx.x;
    if (e < NE) atomicAdd(&g_cnt[load_idx(ei, NE + e, is64)], 1);
}

// ---------------- K3: single-block exclusive scan (50000 elems) ----------------
__global__ void k_scan() {
    __shared__ int warpsum[32];
    __shared__ int s_carry;
    int tid = threadIdx.x;
    if (tid == 0) s_carry = 0;
    __syncthreads();
    for (int base = 0; base < NN; base += 1024) {
        int i = base + tid;
        int v = (i < NN) ? g_cnt[i] : 0;
        int xv = v;
#pragma unroll
        for (int o = 1; o < 32; o <<= 1) {
            int y = __shfl_up_sync(0xffffffffu, xv, o);
            if ((tid & 31) >= o) xv += y;
        }
        if ((tid & 31) == 31) warpsum[tid >> 5] = xv;
        __syncthreads();
        if (tid < 32) {
            int w = warpsum[tid];
#pragma unroll
            for (int o = 1; o < 32; o <<= 1) {
                int y = __shfl_up_sync(0xffffffffu, w, o);
                if (tid >= o) w += y;
            }
            warpsum[tid] = w;
        }
        __syncthreads();
        int incl = xv + ((tid >= 32) ? warpsum[(tid >> 5) - 1] : 0);
        int excl = incl - v + s_carry;
        if (i < NN) { g_off[i] = excl; g_cur[i] = excl; }
        __syncthreads();
        if (tid == 1023) s_carry += incl;
        __syncthreads();
    }
    if (tid == 0) g_off[NN] = NE;
}

// ---------------- K4: bucket scatter (CSR by dst) ----------------
__global__ void k_scatter(const void* __restrict__ ei) {
    int is64 = (g_probe == 0);
    int e = blockIdx.x * blockDim.x + threadIdx.x;
    if (e < NE) {
        int s = load_idx(ei, e, is64);
        int d = load_idx(ei, NE + e, is64);
        int pos = atomicAdd(&g_cur[d], 1);
        if (pos < NE) g_srcs[pos] = s;
    }
}

// ---------------- K5: warp-per-node online-softmax aggregation ----------------
__global__ void k_aggr(const float* __restrict__ att, const float* __restrict__ bias) {
    int i = (blockIdx.x * blockDim.x + threadIdx.x) >> 5;
    int lane = threadIdx.x & 31;
    if (i >= NN) return;

    float2 a  = *(const float2*)(att + (lane << 1));
    float2 xr = *(const float2*)(g_xr + (size_t)i * HC + (lane << 1));

    // self loop seeds the online softmax
    float2 vs = *(const float2*)(g_xl + (size_t)i * HC + (lane << 1));
    float t0 = vs.x + xr.x, t1 = vs.y + xr.y;
    float p = fmaxf(t0, 0.2f * t0) * a.x + fmaxf(t1, 0.2f * t1) * a.y;
#pragma unroll
    for (int o = 16; o; o >>= 1) p += __shfl_xor_sync(0xffffffffu, p, o);
    float m = p, d = 1.0f, acc0 = vs.x, acc1 = vs.y;

    int e = g_off[i], end = g_off[i + 1];
    for (; e < end; e++) {
        int j = g_srcs[e];
        float2 v = *(const float2*)(g_xl + (size_t)j * HC + (lane << 1));
        float u0 = v.x + xr.x, u1 = v.y + xr.y;
        float q = fmaxf(u0, 0.2f * u0) * a.x + fmaxf(u1, 0.2f * u1) * a.y;
#pragma unroll
        for (int o = 16; o; o >>= 1) q += __shfl_xor_sync(0xffffffffu, q, o);
        float nm = fmaxf(m, q);
        float s  = __expf(m - nm);
        float pe = __expf(q - nm);
        d    = d * s + pe;
        acc0 = acc0 * s + pe * v.x;
        acc1 = acc1 * s + pe * v.y;
        m = nm;
    }

    float inv = 1.0f / (d + 1e-16f);
    float h0 = acc0 * inv + bias[(lane << 1) + 0];
    float h1 = acc1 * inv + bias[(lane << 1) + 1];
    h0 = (h0 > 0.0f) ? h0 : expm1f(h0);   // ELU
    h1 = (h1 > 0.0f) ? h1 : expm1f(h1);
    *(float2*)(g_hid + (size_t)i * HC + (lane << 1)) = make_float2(h0, h1);
}

// ---------------- K6: final 64x64 GEMM + bias ----------------
__global__ void k_out(const float* __restrict__ blin, float* __restrict__ out) {
    __shared__ __align__(16) float xs2[32 * HC];
    int tid = threadIdx.x;
    int row0 = blockIdx.x * 32;
    int nrows = NN - row0; if (nrows > 32) nrows = 32;

    for (int i = tid; i < 32 * (HC / 4); i += 128) {
        int r = i >> 4;               // 16 float4 per row
        int k4 = (i & 15) << 2;
        if (r < nrows) {
            float4 v = *(const float4*)(g_hid + (size_t)(row0 + r) * HC + k4);
            float* b = xs2 + (r >> 1) * (2 * HC) + (r & 1);
            b[2 * k4 + 0] = v.x; b[2 * k4 + 2] = v.y;
            b[2 * k4 + 4] = v.z; b[2 * k4 + 6] = v.w;
        }
    }
    __syncthreads();

    int warp = tid >> 5, lane = tid & 31;
    int c = lane << 1;                 // 2 consecutive output channels
    ull acc[4][2];
#pragma unroll
    for (int q = 0; q < 4; q++) { acc[q][0] = 0ull; acc[q][1] = 0ull; }

    const float* xb = xs2 + (warp * 4) * (2 * HC);
#pragma unroll 8
    for (int k = 0; k < HC; k++) {
        float2 w = *(const float2*)(g_Wlt + (k << 6) + c);
        ull w0 = pack2(w.x, w.x), w1 = pack2(w.y, w.y);
#pragma unroll
        for (int q = 0; q < 4; q++) {
            ull xp = *(const ull*)(xb + q * (2 * HC) + 2 * k);
            ffma2(acc[q][0], xp, w0);
            ffma2(acc[q][1], xp, w1);
        }
    }

    float b0 = blin[c], b1 = blin[c + 1];
#pragma unroll
    for (int q = 0; q < 4; q++) {
        int re = row0 + warp * 8 + q * 2;
        if (re >= NN) break;
        float lo0, hi0, lo1, hi1;
        unpack2(acc[q][0], lo0, hi0);
        unpack2(acc[q][1], lo1, hi1);
        *(float2*)(out + (size_t)re * OC + c) = make_float2(lo0 + b0, lo1 + b1);
        if (re + 1 < NN)
            *(float2*)(out + (size_t)(re + 1) * OC + c) = make_float2(hi0 + b0, hi1 + b1);
    }
}

// ---------------- launch ----------------
extern "C" void kernel_launch(void* const* d_in, const int* in_sizes, int n_in,
                              void* d_out, int out_size) {
    const float* x     = (const float*)d_in[0];
    const void*  ei    = d_in[1];            // int32 or int64; detected on device
    // d_in[2] edge_weight: unused by reference
    const float* Wl    = (const float*)d_in[3];
    const float* Wr    = (const float*)d_in[4];
    const float* att   = (const float*)d_in[5];
    const float* bconv = (const float*)d_in[6];
    const float* Wlin  = (const float*)d_in[7];
    const float* blin  = (const float*)d_in[8];
    float* out = (float*)d_out;

    k_pre<<<196, 256>>>(Wl, Wr, Wlin);
    k_detect<<<592, 256>>>((const int*)ei);
    k_gemm1<<<(NN + 31) / 32, 128>>>(x);
    k_hist<<<(NE + 255) / 256, 256>>>(ei);
    k_scan<<<1, 1024>>>();
    k_scatter<<<(NE + 255) / 256, 256>>>(ei);
    k_aggr<<<(NN * 32 + 255) / 256, 256>>>(att, bconv);
    k_out<<<(NN + 31) / 32, 128>>>(blin, out);
}